// round 17
// baseline (speedup 1.0000x reference)
#include <cuda_runtime.h>
#include <cuda_bf16.h>
#include <cuda_fp16.h>
#include <math.h>
#include <stdint.h>

#define B 4
#define N 2048
#define D 1024
#define H 64
#define BN (B*N)            // 8192
#define SCALE 0.125f
#define CLOG2E 0.18033688011112042f   // SCALE * log2(e)
#define NB2 16              // N/128
#define NPAIR2 (NB2*(NB2+1)/2)   // 136
#define NCHUNK 8

// ---- scratch (device globals) ----
__device__ __nv_bfloat16 g_bthi[3*H*D];   // [which*64+n][k] transposed weights, hi
__device__ __nv_bfloat16 g_btlo[3*H*D];
__device__ __nv_bfloat16 g_qkhi[2*BN*H];  // q,k bf16 hi ([row][64])
__device__ __nv_bfloat16 g_qklo[2*BN*H];
__device__ float g_v[BN*H];
__device__ __half g_S16[(size_t)B*N*N];   // t = score*SCALE*log2e, fp16, [r][c]
__device__ float g_m[BN];                 // per-row max of t (masked)
__device__ __half g_vhi[BN*H];            // v * linv, fp16 hi
__device__ __half g_vlo[BN*H];
__device__ float g_part[(size_t)NCHUNK*BN*H];

// ============================================================
// helpers
// ============================================================
__device__ __forceinline__ uint32_t smem_u32(const void* p) {
    uint32_t a;
    asm("{ .reg .u64 t; cvta.to.shared.u64 t, %1; cvt.u32.u64 %0, t; }" : "=r"(a) : "l"(p));
    return a;
}
static __device__ __forceinline__ uint32_t swz128(uint32_t off) { return off ^ ((off >> 3) & 0x70); }

__device__ __forceinline__ float ex2f(float x) {
    float r;
    asm("ex2.approx.ftz.f32 %0, %1;" : "=f"(r) : "f"(x));
    return r;
}

__device__ __forceinline__ void ldsm_x4(uint32_t addr, uint32_t& r0, uint32_t& r1, uint32_t& r2, uint32_t& r3) {
    asm volatile("ldmatrix.sync.aligned.m8n8.x4.shared.b16 {%0,%1,%2,%3}, [%4];"
                 : "=r"(r0), "=r"(r1), "=r"(r2), "=r"(r3) : "r"(addr));
}
__device__ __forceinline__ void ldsm_x4_t(uint32_t addr, uint32_t& r0, uint32_t& r1, uint32_t& r2, uint32_t& r3) {
    asm volatile("ldmatrix.sync.aligned.m8n8.x4.trans.shared.b16 {%0,%1,%2,%3}, [%4];"
                 : "=r"(r0), "=r"(r1), "=r"(r2), "=r"(r3) : "r"(addr));
}
__device__ __forceinline__ void mma_bf16(float* c, const uint32_t* a, uint32_t b0, uint32_t b1) {
    asm volatile("mma.sync.aligned.m16n8k16.row.col.f32.bf16.bf16.f32 "
                 "{%0,%1,%2,%3}, {%4,%5,%6,%7}, {%8,%9}, {%0,%1,%2,%3};"
                 : "+f"(c[0]), "+f"(c[1]), "+f"(c[2]), "+f"(c[3])
                 : "r"(a[0]), "r"(a[1]), "r"(a[2]), "r"(a[3]), "r"(b0), "r"(b1));
}
__device__ __forceinline__ void mma_fp16(float* c, const uint32_t* a, uint32_t b0, uint32_t b1) {
    asm volatile("mma.sync.aligned.m16n8k16.row.col.f32.f16.f16.f32 "
                 "{%0,%1,%2,%3}, {%4,%5,%6,%7}, {%8,%9}, {%0,%1,%2,%3};"
                 : "+f"(c[0]), "+f"(c[1]), "+f"(c[2]), "+f"(c[3])
                 : "r"(a[0]), "r"(a[1]), "r"(a[2]), "r"(a[3]), "r"(b0), "r"(b1));
}
#define CP_ASYNC16(dst, src) asm volatile("cp.async.cg.shared.global [%0], [%1], 16;" :: "r"(dst), "l"(src))
#define CP_COMMIT() asm volatile("cp.async.commit_group;" ::: "memory")
#define CP_WAIT1() asm volatile("cp.async.wait_group 1;" ::: "memory")
#define CP_WAIT0() asm volatile("cp.async.wait_group 0;" ::: "memory")

// ============================================================
// Kernel 0: transpose+split W -> [which*64+n][k], hi/lo
// ============================================================
__global__ __launch_bounds__(256) void convert_w_kernel(
    const float* __restrict__ Wq, const float* __restrict__ Wk, const float* __restrict__ Wv)
{
    int n = blockIdx.x;
    int which = blockIdx.y;
    const float* __restrict__ W = (which == 0) ? Wq : (which == 1) ? Wk : Wv;
    int base = which * H * D + n * D;
    for (int it = 0; it < 4; it++) {
        int k = threadIdx.x + it * 256;
        float w = W[(size_t)k * H + n];
        __nv_bfloat16 hi = __float2bfloat16(w);
        __nv_bfloat16 lo = __float2bfloat16(w - __bfloat162float(hi));
        g_bthi[base + k] = hi;
        g_btlo[base + k] = lo;
    }
}

// ============================================================
// Kernel 1: fused QKV. CTA tile 64(M) x 192(N=q|k|v), K-chunks of 64.
// ============================================================
#define QKV_BUFSZ 65536
#define QAHI(b) ((b) * QKV_BUFSZ)
#define QALO(b) ((b) * QKV_BUFSZ + 8192)
#define QBHI(b) ((b) * QKV_BUFSZ + 16384)
#define QBLO(b) ((b) * QKV_BUFSZ + 40960)

__global__ __launch_bounds__(256, 1) void qkv_mma_kernel(
    const float* __restrict__ x,
    const float* __restrict__ bq, const float* __restrict__ bk, const float* __restrict__ bv)
{
    extern __shared__ __align__(16) char sm[];
    const uint32_t smb = smem_u32(sm);

    const int tid = threadIdx.x;
    const int w = tid >> 5, l = tid & 31;
    const int wm = w & 1, wn = w >> 1;
    const int row0 = blockIdx.x * 64;

    float4 xr[2][2];
    float acc[2][6][4] = {};

    auto prefetch = [&](int c) {
        int k0 = c * 64;
        #pragma unroll
        for (int it = 0; it < 2; it++) {
            int lin = tid + it * 256;
            int r = lin >> 3, c8 = lin & 7;
            const float* src = x + (size_t)(row0 + r) * D + k0 + c8 * 8;
            xr[it][0] = *(const float4*)src;
            xr[it][1] = *(const float4*)(src + 4);
        }
    };
    auto sts_convert = [&](int buf) {
        #pragma unroll
        for (int it = 0; it < 2; it++) {
            int lin = tid + it * 256;
            int r = lin >> 3, c8 = lin & 7;
            float f[8] = {xr[it][0].x, xr[it][0].y, xr[it][0].z, xr[it][0].w,
                          xr[it][1].x, xr[it][1].y, xr[it][1].z, xr[it][1].w};
            __nv_bfloat16 hi[8], lo[8];
            #pragma unroll
            for (int u = 0; u < 8; u++) {
                hi[u] = __float2bfloat16(f[u]);
                lo[u] = __float2bfloat16(f[u] - __bfloat162float(hi[u]));
            }
            uint32_t off = swz128(r * 128 + c8 * 16);
            __nv_bfloat162 h2[4] = {{hi[0],hi[1]},{hi[2],hi[3]},{hi[4],hi[5]},{hi[6],hi[7]}};
            __nv_bfloat162 l2[4] = {{lo[0],lo[1]},{lo[2],lo[3]},{lo[4],lo[5]},{lo[6],lo[7]}};
            *(uint4*)(sm + QAHI(buf) + off) = *(uint4*)h2;
            *(uint4*)(sm + QALO(buf) + off) = *(uint4*)l2;
        }
    };
    auto issueB = [&](int c, int buf) {
        int k0 = c * 64;
        #pragma unroll
        for (int it = 0; it < 6; it++) {
            int lin = tid + it * 256;
            int r = lin >> 3, c16 = lin & 7;
            uint32_t off = swz128(r * 128 + c16 * 16);
            CP_ASYNC16(smb + QBHI(buf) + off, g_bthi + (size_t)r * D + k0 + c16 * 8);
            CP_ASYNC16(smb + QBLO(buf) + off, g_btlo + (size_t)r * D + k0 + c16 * 8);
        }
    };

    prefetch(0);
    issueB(0, 0); CP_COMMIT();

    for (int c = 0; c < 16; c++) {
        const int buf = c & 1;
        sts_convert(buf);
        if (c < 15) {
            issueB(c + 1, buf ^ 1); CP_COMMIT();
            prefetch(c + 1);
            CP_WAIT1();
        } else {
            CP_WAIT0();
        }
        __syncthreads();

        const uint32_t aHi = smb + QAHI(buf), aLo = smb + QALO(buf);
        const uint32_t bHi = smb + QBHI(buf), bLo = smb + QBLO(buf);
        #pragma unroll
        for (int ks = 0; ks < 4; ks++) {
            const int kb = ks * 32;
            uint32_t ah[2][4], al[2][4];
            #pragma unroll
            for (int t = 0; t < 2; t++) {
                int row = wm * 32 + t * 16 + (l & 7) + (l & 8);
                uint32_t off = swz128(row * 128 + kb + (l & 16));
                ldsm_x4(aHi + off, ah[t][0], ah[t][1], ah[t][2], ah[t][3]);
                ldsm_x4(aLo + off, al[t][0], al[t][1], al[t][2], al[t][3]);
            }
            uint32_t bh[3][4], bl[3][4];
            #pragma unroll
            for (int bp = 0; bp < 3; bp++) {
                int n = wn * 48 + bp * 16 + ((l & 16) >> 1) + (l & 7);
                uint32_t off = swz128(n * 128 + kb + ((l & 8) << 1));
                ldsm_x4(bHi + off, bh[bp][0], bh[bp][1], bh[bp][2], bh[bp][3]);
                ldsm_x4(bLo + off, bl[bp][0], bl[bp][1], bl[bp][2], bl[bp][3]);
            }
            #pragma unroll
            for (int t = 0; t < 2; t++)
                #pragma unroll
                for (int u = 0; u < 6; u++) {
                    int bp = u >> 1, s = (u & 1) * 2;
                    mma_bf16(acc[t][u], ah[t], bh[bp][s], bh[bp][s + 1]);
                    mma_bf16(acc[t][u], al[t], bh[bp][s], bh[bp][s + 1]);
                    mma_bf16(acc[t][u], ah[t], bl[bp][s], bl[bp][s + 1]);
                }
        }
        __syncthreads();
    }

    const int l4 = l >> 2, l2 = 2 * (l & 3);
    #pragma unroll
    for (int t = 0; t < 2; t++) {
        #pragma unroll
        for (int u = 0; u < 6; u++) {
            int r = row0 + wm * 32 + t * 16 + l4;
            int nn = wn * 48 + u * 8 + l2;
            int which = nn >> 6, col = nn & 63;
            const float* bias = (which == 0) ? bq : (which == 1) ? bk : bv;
            float b0 = bias[col], b1 = bias[col + 1];
            float v0 = acc[t][u][0] + b0, v1 = acc[t][u][1] + b1;
            float v2 = acc[t][u][2] + b0, v3 = acc[t][u][3] + b1;
            if (which == 2) {
                float2 p0 = {v0, v1}, p1 = {v2, v3};
                *(float2*)&g_v[(size_t)r * H + col] = p0;
                *(float2*)&g_v[(size_t)(r + 8) * H + col] = p1;
            } else {
                size_t off = (size_t)which * BN * H;
                __nv_bfloat16 h0 = __float2bfloat16(v0), h1 = __float2bfloat16(v1);
                __nv_bfloat16 h2 = __float2bfloat16(v2), h3 = __float2bfloat16(v3);
                *(__nv_bfloat162*)&g_qkhi[off + (size_t)r * H + col] = __nv_bfloat162(h0, h1);
                *(__nv_bfloat162*)&g_qkhi[off + (size_t)(r + 8) * H + col] = __nv_bfloat162(h2, h3);
                __nv_bfloat162 lo0(__float2bfloat16(v0 - __bfloat162float(h0)),
                                   __float2bfloat16(v1 - __bfloat162float(h1)));
                __nv_bfloat162 lo1(__float2bfloat16(v2 - __bfloat162float(h2)),
                                   __float2bfloat16(v3 - __bfloat162float(h3)));
                *(__nv_bfloat162*)&g_qklo[off + (size_t)r * H + col] = lo0;
                *(__nv_bfloat162*)&g_qklo[off + (size_t)(r + 8) * H + col] = lo1;
            }
        }
    }
}

// ============================================================
// Kernel 2: S = Q.K^T (x SCALE*log2e), fp16 output, 128x128 tiles, 512 threads.
// ============================================================
__global__ __launch_bounds__(512) void s_mma_kernel()
{
    extern __shared__ char sms[];
    const uint32_t smb = smem_u32(sms);

    int p = blockIdx.x;
    int bi = 0;
    while (p >= NB2 - bi) { p -= NB2 - bi; bi++; }
    int bj = bi + p;
    int b = blockIdx.y;

    const int tid = threadIdx.x;
    const int w = tid >> 5, l = tid & 31;
    const int wm = w & 3, wn = w >> 2;

    const __nv_bfloat16* __restrict__ src[4] = {
        g_qkhi + (size_t)(b * N + bi * 128) * H,
        g_qklo + (size_t)(b * N + bi * 128) * H,
        g_qkhi + (size_t)BN * H + (size_t)(b * N + bj * 128) * H,
        g_qklo + (size_t)BN * H + (size_t)(b * N + bj * 128) * H
    };
    #pragma unroll
    for (int tile = 0; tile < 4; tile++) {
        #pragma unroll
        for (int it = 0; it < 2; it++) {
            int lin = tid + it * 512;
            int r = lin >> 3, c16 = lin & 7;
            uint4 v = *(const uint4*)(src[tile] + (size_t)r * H + c16 * 8);
            *(uint4*)(sms + tile * 16384 + swz128(r * 128 + c16 * 16)) = v;
        }
    }
    __syncthreads();

    float acc[2][4][4] = {};
    #pragma unroll
    for (int pass = 0; pass < 3; pass++) {
        const uint32_t aBase = smb + ((pass == 1) ? 16384 : 0);
        const uint32_t bBase = smb + ((pass == 2) ? 49152 : 32768);
        #pragma unroll
        for (int ks = 0; ks < 4; ks++) {
            const int kb = ks * 32;
            uint32_t a[2][4];
            #pragma unroll
            for (int t = 0; t < 2; t++) {
                int row = wm * 32 + t * 16 + (l & 7) + (l & 8);
                ldsm_x4(aBase + swz128(row * 128 + kb + (l & 16)), a[t][0], a[t][1], a[t][2], a[t][3]);
            }
            uint32_t bfr[2][4];
            #pragma unroll
            for (int bp = 0; bp < 2; bp++) {
                int n = wn * 32 + bp * 16 + ((l & 16) >> 1) + (l & 7);
                ldsm_x4(bBase + swz128(n * 128 + kb + ((l & 8) << 1)),
                        bfr[bp][0], bfr[bp][1], bfr[bp][2], bfr[bp][3]);
            }
            #pragma unroll
            for (int t = 0; t < 2; t++)
                #pragma unroll
                for (int u = 0; u < 4; u++)
                    mma_bf16(acc[t][u], a[t], bfr[u >> 1][(u & 1) * 2], bfr[u >> 1][(u & 1) * 2 + 1]);
        }
    }

    const int l4 = l >> 2, l2 = 2 * (l & 3);
    #pragma unroll
    for (int t = 0; t < 2; t++) {
        #pragma unroll
        for (int u = 0; u < 4; u++) {
            int i = bi * 128 + wm * 32 + t * 16 + l4;
            int j = bj * 128 + wn * 32 + u * 8 + l2;
            __half2 q0 = __floats2half2_rn(acc[t][u][0] * CLOG2E, acc[t][u][1] * CLOG2E);
            __half2 q1 = __floats2half2_rn(acc[t][u][2] * CLOG2E, acc[t][u][3] * CLOG2E);
            *(__half2*)&g_S16[((size_t)(b * N + i)) * N + j] = q0;
            *(__half2*)&g_S16[((size_t)(b * N + i + 8)) * N + j] = q1;
        }
    }
}

// ============================================================
// Kernel 3: per-row stats only: m = masked max(t), linv = 1/sum(ex2(t-m)).
// 4 rows/block, 64 threads/row, 4 uint4 (8 halves) slots per thread.
// Writes g_m + linv-scaled V (fp16 hi/lo). No E materialization.
// ============================================================
__global__ __launch_bounds__(256) void stats_kernel()
{
    const int sub = threadIdx.x >> 6;          // row within group (0..3)
    const int t64 = threadIdx.x & 63;
    const int lane = threadIdx.x & 31;
    const int wh = (threadIdx.x >> 5) & 1;
    const int row = blockIdx.x * 4 + sub;      // b*N + r
    const int j = row & (N - 1);
    const int i0 = j & ~127;
    const int L = N - i0;                      // 128..2048
    const int jrel = j - i0;                   // 0..127
    const __half* __restrict__ base = g_S16 + (size_t)row * N + i0;

    uint4 raw[4];
    #pragma unroll
    for (int s = 0; s < 4; s++) {
        int e0 = s * 512 + t64 * 8;
        if (e0 < L) raw[s] = *(const uint4*)&base[e0];
        else        raw[s] = make_uint4(0xFC00FC00u, 0xFC00FC00u, 0xFC00FC00u, 0xFC00FC00u);
    }
    // causal mask: elements < jrel live in slot 0 (first 512 >= 128 cols)
    if (t64 * 8 < jrel) {
        uint32_t* pr = &raw[0].x;
        #pragma unroll
        for (int p = 0; p < 4; p++) {
            int e0 = t64 * 8 + p * 2;
            if (e0 + 1 < jrel)      pr[p] = 0xFC00FC00u;
            else if (e0 < jrel)     pr[p] = (pr[p] & 0xFFFF0000u) | 0x0000FC00u;
        }
    }

    // max pass
    __shared__ float sm2[4][2], ss2[4][2];
    float m = -INFINITY;
    #pragma unroll
    for (int s = 0; s < 4; s++) {
        const __half2* hp = (const __half2*)&raw[s];
        #pragma unroll
        for (int p = 0; p < 4; p++) {
            float2 f = __half22float2(hp[p]);
            m = fmaxf(m, fmaxf(f.x, f.y));
        }
    }
    #pragma unroll
    for (int o = 16; o > 0; o >>= 1) m = fmaxf(m, __shfl_xor_sync(0xFFFFFFFFu, m, o));
    if (lane == 0) sm2[sub][wh] = m;
    __syncthreads();
    m = fmaxf(sm2[sub][0], sm2[sub][1]);

    // exp-sum pass
    float ls = 0.0f;
    #pragma unroll
    for (int s = 0; s < 4; s++) {
        const __half2* hp = (const __half2*)&raw[s];
        #pragma unroll
        for (int p = 0; p < 4; p++) {
            float2 f = __half22float2(hp[p]);
            ls += ex2f(f.x - m) + ex2f(f.y - m);
        }
    }
    #pragma unroll
    for (int o = 16; o > 0; o >>= 1) ls += __shfl_xor_sync(0xFFFFFFFFu, ls, o);
    if (lane == 0) ss2[sub][wh] = ls;
    __syncthreads();
    const float linv = 1.0f / (ss2[sub][0] + ss2[sub][1]);

    if (t64 == 0) g_m[row] = m;

    // fused v scaling: v'[j] = linv * v[j], fp16 hi/lo
    if (t64 < 16) {
        float4 v = *(const float4*)&g_v[(size_t)row * H + t64 * 4];
        float f[4] = {v.x * linv, v.y * linv, v.z * linv, v.w * linv};
        __half hi[4], lo[4];
        #pragma unroll
        for (int u = 0; u < 4; u++) {
            hi[u] = __float2half(f[u]);
            lo[u] = __float2half(f[u] - __half2float(hi[u]));
        }
        __half2 h01(hi[0], hi[1]), h23(hi[2], hi[3]);
        __half2 l01(lo[0], lo[1]), l23(lo[2], lo[3]);
        uint2 wha = {*(uint32_t*)&h01, *(uint32_t*)&h23};
        uint2 wla = {*(uint32_t*)&l01, *(uint32_t*)&l23};
        *(uint2*)&g_vhi[(size_t)row * H + t64 * 4] = wha;
        *(uint2*)&g_vlo[(size_t)row * H + t64 * 4] = wla;
    }
}

// ============================================================
// Kernel 4: AV partials via fp16 mma; exp applied inline while staging tiles.
// 512 threads (4i x 4h warps, warp 32x16).
// ============================================================
__global__ __launch_bounds__(512) void av_mma_kernel()
{
    int p = blockIdx.x, b = blockIdx.y;
    int bi = 0;
    for (;;) {
        int nc = ((2 * bi + 1) >> 2) + 1;
        if (p < nc) break;
        p -= nc; bi++;
    }
    int chunk = p;
    int i0 = bi * 128;
    int jb0 = chunk * 4;
    int jb_end = min(jb0 + 4, 2 * bi + 2);

    __shared__ __align__(16) char smE[16384];
    __shared__ __align__(16) char smVh[8192];
    __shared__ __align__(16) char smVl[8192];
    const uint32_t eb = smem_u32(smE), vhb = smem_u32(smVh), vlb = smem_u32(smVl);

    int tid = threadIdx.x;
    int w = tid >> 5, l = tid & 31;
    int im = w & 3, ih = w >> 2;

    float acc[2][2][4] = {};

    for (int jb = jb0; jb < jb_end; jb++) {
        int j0 = jb * 64;
        __syncthreads();
        // stage E tile: load fp16 t, e = ex2(t - m_j), causal mask, pack fp16
        #pragma unroll
        for (int it = 0; it < 2; it++) {
            int lin = tid + it * 512;
            int jr = lin >> 4, c16 = lin & 15;
            int half = c16 >> 3, ic16 = c16 & 7;
            int jglob = j0 + jr;
            int ibase = i0 + c16 * 8;
            uint4 traw = *(const uint4*)&g_S16[((size_t)b * N + jglob) * N + ibase];
            float mj = g_m[b * N + jglob];
            const __half2* hp = (const __half2*)&traw;
            uint32_t outw[4];
            #pragma unroll
            for (int q = 0; q < 4; q++) {
                float2 f = __half22float2(hp[q]);
                float e0 = ex2f(f.x - mj);
                float e1 = ex2f(f.y - mj);
                if (ibase + q * 2 < jglob)     e0 = 0.0f;   // i < j -> masked
                if (ibase + q * 2 + 1 < jglob) e1 = 0.0f;
                __half2 h = __floats2half2_rn(e0, e1);
                outw[q] = *(uint32_t*)&h;
            }
            uint4 ov = {outw[0], outw[1], outw[2], outw[3]};
            *(uint4*)(smE + half * 8192 + swz128(jr * 128 + ic16 * 16)) = ov;
        }
        {
            int jr = tid >> 3, c16 = tid & 7;
            uint4 th = *(const uint4*)&g_vhi[((size_t)b * N + j0 + jr) * H + c16 * 8];
            uint4 tl = *(const uint4*)&g_vlo[((size_t)b * N + j0 + jr) * H + c16 * 8];
            uint32_t off = swz128(jr * 128 + c16 * 16);
            *(uint4*)(smVh + off) = th;
            *(uint4*)(smVl + off) = tl;
        }
        __syncthreads();

        #pragma unroll
        for (int ks = 0; ks < 4; ks++) {
            uint32_t a[2][4];
            #pragma unroll
            for (int t = 0; t < 2; t++) {
                int il = im * 32 + t * 16;
                int half = il >> 6, iin = il & 63;
                int jr = ks * 16 + (l & 7) + ((l & 16) >> 1);
                int ic = iin + (l & 8);
                ldsm_x4_t(eb + half * 8192 + swz128(jr * 128 + ic * 2),
                          a[t][0], a[t][1], a[t][2], a[t][3]);
            }
            uint32_t bh[4], bl[4];
            {
                int jrb = ks * 16 + (l & 7) + (l & 8);
                int hc = ih * 16 + ((l & 16) >> 1);
                uint32_t off = swz128(jrb * 128 + hc * 2);
                ldsm_x4_t(vhb + off, bh[0], bh[1], bh[2], bh[3]);
                ldsm_x4_t(vlb + off, bl[0], bl[1], bl[2], bl[3]);
            }
            #pragma unroll
            for (int t = 0; t < 2; t++)
                #pragma unroll
                for (int n8 = 0; n8 < 2; n8++) {
                    mma_fp16(acc[t][n8], a[t], bh[2 * n8], bh[2 * n8 + 1]);
                    mma_fp16(acc[t][n8], a[t], bl[2 * n8], bl[2 * n8 + 1]);
                }
        }
    }

    const int l4 = l >> 2, l2 = 2 * (l & 3);
    #pragma unroll
    for (int t = 0; t < 2; t++) {
        #pragma unroll
        for (int n8 = 0; n8 < 2; n8++) {
            int i = i0 + im * 32 + t * 16 + l4;
            int h = ih * 16 + n8 * 8 + l2;
            float2 p0 = {acc[t][n8][0], acc[t][n8][1]};
            float2 p1 = {acc[t][n8][2], acc[t][n8][3]};
            *(float2*)&g_part[((size_t)chunk * BN + b * N + i) * H + h] = p0;
            *(float2*)&g_part[((size_t)chunk * BN + b * N + i + 8) * H + h] = p1;
        }
    }
}

// ============================================================
// Kernel 5: reduce partial chunks
// ============================================================
__global__ __launch_bounds__(256) void reduce_kernel(float* __restrict__ out)
{
    int idx = blockIdx.x * 256 + threadIdx.x;
    if (idx >= BN * H) return;
    int row = idx / H;
    int i = row & (N - 1);
    int nch = (i >> 8) + 1;
    float s = 0.0f;
    for (int c = 0; c < nch; c++)
        s += g_part[(size_t)c * BN * H + idx];
    out[idx] = s;
}

// ============================================================
extern "C" void kernel_launch(void* const* d_in, const int* in_sizes, int n_in,
                              void* d_out, int out_size)
{
    const float* x  = (const float*)d_in[0];
    const float* Wq = (const float*)d_in[1];
    const float* bq = (const float*)d_in[2];
    const float* Wk = (const float*)d_in[3];
    const float* bk = (const float*)d_in[4];
    const float* Wv = (const float*)d_in[5];
    const float* bv = (const float*)d_in[6];
    float* out = (float*)d_out;

    cudaFuncSetAttribute(qkv_mma_kernel, cudaFuncAttributeMaxDynamicSharedMemorySize, 2 * QKV_BUFSZ);
    cudaFuncSetAttribute(s_mma_kernel, cudaFuncAttributeMaxDynamicSharedMemorySize, 65536);

    convert_w_kernel<<<dim3(H, 3), 256>>>(Wq, Wk, Wv);
    qkv_mma_kernel<<<BN / 64, 256, 2 * QKV_BUFSZ>>>(x, bq, bk, bv);
    s_mma_kernel<<<dim3(NPAIR2, B), 512, 65536>>>();
    stats_kernel<<<BN / 4, 256>>>();
    av_mma_kernel<<<dim3(72, B), 512>>>();
    reduce_kernel<<<(BN * H + 255) / 256, 256>>>(out);
}